// round 9
// baseline (speedup 1.0000x reference)
#include <cuda_runtime.h>
#include <cuda_bf16.h>
#include <math.h>
#include <cstdint>

#define SEQ 4096
#define DMODEL 1024
#define NHEAD 16
#define DK 64

// ---------------------------------------------------------------------------
// Scratch (device globals — no runtime allocation allowed)
// ---------------------------------------------------------------------------
__device__ __align__(16) float g_Q[SEQ * DMODEL];
__device__ __align__(16) float g_K[SEQ * DMODEL];

__device__ __align__(16) __nv_bfloat16 g_xhi[SEQ * DMODEL];
__device__ __align__(16) __nv_bfloat16 g_xlo[SEQ * DMODEL];
__device__ __align__(16) __nv_bfloat16 g_whi[4 * DMODEL * DMODEL];
__device__ __align__(16) __nv_bfloat16 g_wlo[4 * DMODEL * DMODEL];
__device__ __align__(16) __nv_bfloat16 g_chi[SEQ * DMODEL];
__device__ __align__(16) __nv_bfloat16 g_clo[SEQ * DMODEL];

__device__ __align__(16) __nv_bfloat16 g_qhi[SEQ * DMODEL];
__device__ __align__(16) __nv_bfloat16 g_qlo[SEQ * DMODEL];
__device__ __align__(16) __nv_bfloat16 g_khi[SEQ * DMODEL];
__device__ __align__(16) __nv_bfloat16 g_klo[SEQ * DMODEL];
__device__ __align__(16) __nv_bfloat16 g_vhi[SEQ * DMODEL];
__device__ __align__(16) __nv_bfloat16 g_vlo[SEQ * DMODEL];

// ---------------------------------------------------------------------------
// Baseline-PTX helpers
// ---------------------------------------------------------------------------
__device__ __forceinline__ uint32_t smem_u32(const void* p) {
    uint32_t a;
    asm("{ .reg .u64 t; cvta.to.shared.u64 t, %1; cvt.u32.u64 %0, t; }"
        : "=r"(a) : "l"(p));
    return a;
}

__device__ __forceinline__ void cp16(uint32_t dst, const void* src) {
    asm volatile("cp.async.cg.shared.global [%0], [%1], 16;"
        :: "r"(dst), "l"(src) : "memory");
}
#define CP_COMMIT() asm volatile("cp.async.commit_group;" ::: "memory")
#define CP_WAIT1()  asm volatile("cp.async.wait_group 1;" ::: "memory")
#define CP_WAIT0()  asm volatile("cp.async.wait_group 0;" ::: "memory")

__device__ __forceinline__ void ldsm4(uint32_t r[4], uint32_t addr) {
    asm volatile("ldmatrix.sync.aligned.m8n8.x4.shared.b16 {%0,%1,%2,%3}, [%4];"
        : "=r"(r[0]), "=r"(r[1]), "=r"(r[2]), "=r"(r[3]) : "r"(addr));
}
__device__ __forceinline__ void ldsm4t(uint32_t r[4], uint32_t addr) {
    asm volatile("ldmatrix.sync.aligned.m8n8.x4.trans.shared.b16 {%0,%1,%2,%3}, [%4];"
        : "=r"(r[0]), "=r"(r[1]), "=r"(r[2]), "=r"(r[3]) : "r"(addr));
}

__device__ __forceinline__ void mma_bf16(float c[4], const uint32_t a[4],
                                         uint32_t b0, uint32_t b1) {
    asm volatile(
        "mma.sync.aligned.m16n8k16.row.col.f32.bf16.bf16.f32 "
        "{%0,%1,%2,%3}, {%4,%5,%6,%7}, {%8,%9}, {%0,%1,%2,%3};"
        : "+f"(c[0]), "+f"(c[1]), "+f"(c[2]), "+f"(c[3])
        : "r"(a[0]), "r"(a[1]), "r"(a[2]), "r"(a[3]), "r"(b0), "r"(b1));
}

__device__ __forceinline__ void split2(float a, float b, uint32_t& hi, uint32_t& lo) {
    __nv_bfloat16 ha = __float2bfloat16(a);
    __nv_bfloat16 hb = __float2bfloat16(b);
    __nv_bfloat162 hp(ha, hb);
    __nv_bfloat162 lp(__float2bfloat16(a - __bfloat162float(ha)),
                      __float2bfloat16(b - __bfloat162float(hb)));
    hi = *(uint32_t*)&hp;
    lo = *(uint32_t*)&lp;
}

// ---------------------------------------------------------------------------
// Elementwise kernels
// ---------------------------------------------------------------------------
__global__ void split_kernel(const float* __restrict__ in,
                             __nv_bfloat16* __restrict__ hi,
                             __nv_bfloat16* __restrict__ lo, int n4)
{
    int i = blockIdx.x * blockDim.x + threadIdx.x;
    if (i >= n4) return;
    float4 v = ((const float4*)in)[i];
    uint32_t h0, l0, h1, l1;
    split2(v.x, v.y, h0, l0);
    split2(v.z, v.w, h1, l1);
    ((uint2*)hi)[i] = make_uint2(h0, h1);
    ((uint2*)lo)[i] = make_uint2(l0, l1);
}

__global__ void split_w4(const float* __restrict__ w0, const float* __restrict__ w1,
                         const float* __restrict__ w2, const float* __restrict__ w3,
                         __nv_bfloat16* __restrict__ hi, __nv_bfloat16* __restrict__ lo)
{
    const int wsel = blockIdx.y;
    const float* src = (wsel == 0) ? w0 : (wsel == 1) ? w1 : (wsel == 2) ? w2 : w3;
    const int n4 = DMODEL * DMODEL / 4;
    int i = blockIdx.x * blockDim.x + threadIdx.x;
    if (i >= n4) return;
    float4 v = ((const float4*)src)[i];
    uint32_t h0, l0, h1, l1;
    split2(v.x, v.y, h0, l0);
    split2(v.z, v.w, h1, l1);
    const size_t base = (size_t)wsel * DMODEL * DMODEL / 4;
    ((uint2*)hi)[base + i] = make_uint2(h0, h1);
    ((uint2*)lo)[base + i] = make_uint2(l0, l1);
}

__global__ void rope_conv(const float* __restrict__ Q, const float* __restrict__ K,
                          __nv_bfloat16* __restrict__ qhi, __nv_bfloat16* __restrict__ qlo,
                          __nv_bfloat16* __restrict__ khi, __nv_bfloat16* __restrict__ klo)
{
    const int n4 = SEQ * DMODEL / 4;
    int idx = blockIdx.x * blockDim.x + threadIdx.x;
    if (idx >= n4) return;

    const int s   = idx >> 8;
    const int f   = idx & 255;
    const int col = f * 4;
    const int i0  = (col & 63) >> 1;

    const float c1 = -9.210340371976184f / 32.0f;
    const float a0 = (float)s * expf((float)i0 * c1);
    const float a1 = (float)s * expf((float)(i0 + 1) * c1);
    float sn0, cs0, sn1, cs1;
    sincosf(a0, &sn0, &cs0);
    sincosf(a1, &sn1, &cs1);

    float4 q = ((const float4*)Q)[idx];
    float4 k = ((const float4*)K)[idx];

    float qx = (q.x * cs0 - q.y * sn0) * 0.125f;
    float qy = (q.x * sn0 + q.y * cs0) * 0.125f;
    float qz = (q.z * cs1 - q.w * sn1) * 0.125f;
    float qw = (q.z * sn1 + q.w * cs1) * 0.125f;
    float kx = k.x * cs0 - k.y * sn0;
    float ky = k.x * sn0 + k.y * cs0;
    float kz = k.z * cs1 - k.w * sn1;
    float kw = k.z * sn1 + k.w * cs1;

    uint32_t h0, l0, h1, l1;
    split2(qx, qy, h0, l0); split2(qz, qw, h1, l1);
    ((uint2*)qhi)[idx] = make_uint2(h0, h1);
    ((uint2*)qlo)[idx] = make_uint2(l0, l1);
    split2(kx, ky, h0, l0); split2(kz, kw, h1, l1);
    ((uint2*)khi)[idx] = make_uint2(h0, h1);
    ((uint2*)klo)[idx] = make_uint2(l0, l1);
}

// ---------------------------------------------------------------------------
// Tensor-core GEMM: 128x128 CTA tile, 4 warps (2x2), 64x64 warp tile.
// BK=32, TWO-stage cp.async pipeline (round-7 config). hi/lo split, fp32 acc.
// ---------------------------------------------------------------------------
#define BK 32
#define NT (DMODEL / BK)
#define TILE_B (128 * 64)           // 8 KB per operand tile
#define STAGE_B (4 * TILE_B)        // 32 KB

struct GemmCore {
    float acc[4][8][4];
    int r0, c0;
};

__device__ __forceinline__ void gemm_mainloop(
    const __nv_bfloat16* __restrict__ Ahi, const __nv_bfloat16* __restrict__ Alo,
    const __nv_bfloat16* __restrict__ Bhi, const __nv_bfloat16* __restrict__ Blo,
    int bm, int bn, char* smem, GemmCore& core)
{
    const int tid  = threadIdx.x;
    const int wid  = tid >> 5, lane = tid & 31;
    const int wm   = wid & 1;
    const int wn   = wid >> 1;
    const uint32_t sbase = smem_u32(smem);

    const __nv_bfloat16* srcs[4] = {
        Ahi + (size_t)bm * DMODEL, Alo + (size_t)bm * DMODEL,
        Bhi + (size_t)bn * DMODEL, Blo + (size_t)bn * DMODEL };

    auto copy_stage = [&](int s, int k0) {
        const uint32_t stb = sbase + s * STAGE_B;
#pragma unroll
        for (int t = 0; t < 4; t++) {
            const __nv_bfloat16* base = srcs[t];
#pragma unroll
            for (int j = 0; j < 4; j++) {
                const int idx = j * 128 + tid;
                const int r = idx >> 2, c = idx & 3;
                const uint32_t pc = (uint32_t)(c ^ ((r >> 1) & 3));
                cp16(stb + t * TILE_B + (uint32_t)r * 64 + pc * 16,
                     base + (size_t)r * DMODEL + k0 + c * 8);
            }
        }
    };

    const int arow = wm * 64 + (lane & 15);
    const int ac0  = lane >> 4;
    const uint32_t aoff = (uint32_t)arow * 64 +
                          (uint32_t)((ac0 ^ ((arow >> 1) & 3)) * 16);
    const int brow = wn * 64 + ((lane >> 4) << 3) + (lane & 7);
    const int bc0  = (lane >> 3) & 1;
    const uint32_t boff = (uint32_t)brow * 64 +
                          (uint32_t)((bc0 ^ ((brow >> 1) & 3)) * 16);

#pragma unroll
    for (int i = 0; i < 4; i++)
#pragma unroll
        for (int j = 0; j < 8; j++)
#pragma unroll
            for (int q = 0; q < 4; q++) core.acc[i][j][q] = 0.f;

    copy_stage(0, 0);
    CP_COMMIT();

    for (int kt = 0; kt < NT; kt++) {
        const int s = kt & 1;
        if (kt + 1 < NT) {
            copy_stage(s ^ 1, (kt + 1) * BK);
            CP_COMMIT();
            CP_WAIT1();
        } else {
            CP_WAIT0();
        }
        __syncthreads();

        const uint32_t stb  = sbase + s * STAGE_B;
        const uint32_t sAhi = stb + aoff;
        const uint32_t sAlo = stb + TILE_B + aoff;
        const uint32_t sBhi = stb + 2 * TILE_B + boff;
        const uint32_t sBlo = stb + 3 * TILE_B + boff;

#pragma unroll
        for (int ks = 0; ks < 2; ks++) {
            const uint32_t kx = (uint32_t)(ks << 5);
            uint32_t ah[4][4], al[4][4], bh[4][4], bl[4][4];
#pragma unroll
            for (int mf = 0; mf < 4; mf++) {
                ldsm4(ah[mf], (sAhi + mf * 1024) ^ kx);
                ldsm4(al[mf], (sAlo + mf * 1024) ^ kx);
            }
#pragma unroll
            for (int np = 0; np < 4; np++) {
                ldsm4(bh[np], (sBhi + np * 1024) ^ kx);
                ldsm4(bl[np], (sBlo + np * 1024) ^ kx);
            }
#pragma unroll
            for (int mf = 0; mf < 4; mf++) {
#pragma unroll
                for (int nt = 0; nt < 8; nt++) {
                    const int np = nt >> 1, hh = (nt & 1) * 2;
                    mma_bf16(core.acc[mf][nt], ah[mf], bh[np][hh], bh[np][hh + 1]);
                    mma_bf16(core.acc[mf][nt], ah[mf], bl[np][hh], bl[np][hh + 1]);
                    mma_bf16(core.acc[mf][nt], al[mf], bh[np][hh], bh[np][hh + 1]);
                }
            }
        }
        __syncthreads();
    }

    core.r0 = bm + wm * 64 + (lane >> 2);
    core.c0 = bn + wn * 64 + (lane & 3) * 2;
}

__global__ __launch_bounds__(128, 2) void gemm_qkv(
    const __nv_bfloat16* __restrict__ Xhi, const __nv_bfloat16* __restrict__ Xlo,
    const __nv_bfloat16* __restrict__ Whi, const __nv_bfloat16* __restrict__ Wlo,
    float* __restrict__ Qout, float* __restrict__ Kout,
    __nv_bfloat16* __restrict__ Vhi, __nv_bfloat16* __restrict__ Vlo)
{
    extern __shared__ __align__(1024) char smem[];
    const int z = blockIdx.z;
    const size_t woff = (size_t)z * DMODEL * DMODEL;

    GemmCore core;
    gemm_mainloop(Xhi, Xlo, Whi + woff, Wlo + woff,
                  blockIdx.y * 128, blockIdx.x * 128, smem, core);

    if (z < 2) {
        float* C = (z == 0) ? Qout : Kout;
#pragma unroll
        for (int mf = 0; mf < 4; mf++) {
#pragma unroll
            for (int nt = 0; nt < 8; nt++) {
                float* p0 = &C[(size_t)(core.r0 + mf * 16) * DMODEL + core.c0 + nt * 8];
                float* p1 = &C[(size_t)(core.r0 + mf * 16 + 8) * DMODEL + core.c0 + nt * 8];
                *(float2*)p0 = make_float2(core.acc[mf][nt][0], core.acc[mf][nt][1]);
                *(float2*)p1 = make_float2(core.acc[mf][nt][2], core.acc[mf][nt][3]);
            }
        }
    } else {
#pragma unroll
        for (int mf = 0; mf < 4; mf++) {
#pragma unroll
            for (int nt = 0; nt < 8; nt++) {
                const size_t o0 = (size_t)(core.r0 + mf * 16) * DMODEL + core.c0 + nt * 8;
                const size_t o1 = (size_t)(core.r0 + mf * 16 + 8) * DMODEL + core.c0 + nt * 8;
                uint32_t h, l;
                split2(core.acc[mf][nt][0], core.acc[mf][nt][1], h, l);
                *(uint32_t*)&Vhi[o0] = h; *(uint32_t*)&Vlo[o0] = l;
                split2(core.acc[mf][nt][2], core.acc[mf][nt][3], h, l);
                *(uint32_t*)&Vhi[o1] = h; *(uint32_t*)&Vlo[o1] = l;
            }
        }
    }
}

__global__ __launch_bounds__(128, 2) void gemm_tc(
    const __nv_bfloat16* __restrict__ Ahi, const __nv_bfloat16* __restrict__ Alo,
    const __nv_bfloat16* __restrict__ Bhi, const __nv_bfloat16* __restrict__ Blo,
    float* __restrict__ C)
{
    extern __shared__ __align__(1024) char smem[];
    GemmCore core;
    gemm_mainloop(Ahi, Alo, Bhi, Blo, blockIdx.y * 128, blockIdx.x * 128, smem, core);
#pragma unroll
    for (int mf = 0; mf < 4; mf++) {
#pragma unroll
        for (int nt = 0; nt < 8; nt++) {
            float* p0 = &C[(size_t)(core.r0 + mf * 16) * DMODEL + core.c0 + nt * 8];
            float* p1 = &C[(size_t)(core.r0 + mf * 16 + 8) * DMODEL + core.c0 + nt * 8];
            *(float2*)p0 = make_float2(core.acc[mf][nt][0], core.acc[mf][nt][1]);
            *(float2*)p1 = make_float2(core.acc[mf][nt][2], core.acc[mf][nt][3]);
        }
    }
}

// ---------------------------------------------------------------------------
// Tensor-core causal flash attention, full hi/lo split numerics.
// ONE q-tile (128 rows) per CTA, grid (32, NHEAD) = 512 CTAs, launched
// largest-first (qtile = 31 - bx) so the LPT greedy schedule balances the
// causal triangle across the 2-slot-per-SM wave.
// ---------------------------------------------------------------------------
#define ATT_TILE_B 8192
#define ATT_STAGE_B (4 * ATT_TILE_B)
#define ATT_SMEM (32768 + 2 * ATT_STAGE_B)   // 96 KB

__global__ __launch_bounds__(128, 2) void attn_tc(
    const __nv_bfloat16* __restrict__ Qhi, const __nv_bfloat16* __restrict__ Qlo,
    const __nv_bfloat16* __restrict__ Khi, const __nv_bfloat16* __restrict__ Klo,
    const __nv_bfloat16* __restrict__ Vhi, const __nv_bfloat16* __restrict__ Vlo,
    __nv_bfloat16* __restrict__ Chi, __nv_bfloat16* __restrict__ Clo)
{
    extern __shared__ __align__(1024) char smem[];
    const uint32_t sb = smem_u32(smem);
    const uint32_t qhib = sb, qlob = sb + 16384;
    const uint32_t stgb = sb + 32768;

    const int h    = blockIdx.y;
    const int tid  = threadIdx.x;
    const int wid  = tid >> 5, lane = tid & 31;
    const int hcol = h * DK;

    const uint32_t lx = (uint32_t)(lane & 7);
    uint32_t qoff[4], koff[4], voff[4];
#pragma unroll
    for (int ks = 0; ks < 4; ks++) {
        qoff[ks] = (uint32_t)(lane & 15) * 128 +
                   ((uint32_t)(ks * 2 + (lane >> 4)) ^ lx) * 16;
        koff[ks] = (uint32_t)(((lane >> 4) << 3) + (lane & 7)) * 128 +
                   ((uint32_t)(ks * 2 + ((lane >> 3) & 1)) ^ lx) * 16;
        voff[ks] = (uint32_t)(lane & 15) * 128 +
                   ((uint32_t)(ks * 2 + (lane >> 4)) ^ lx) * 16;
    }

    const int qtile = 31 - blockIdx.x;    // largest work first
    const int q0 = qtile * 128;
    const int ntiles = qtile * 2 + 2;

    // Q (hi+lo) tile
#pragma unroll
    for (int j = 0; j < 8; j++) {
        const int idx = j * 128 + tid;
        const int r = idx >> 3, c = idx & 7;
        const uint32_t off = (uint32_t)r * 128 + ((uint32_t)c ^ (uint32_t)(r & 7)) * 16;
        const size_t g = (size_t)(q0 + r) * DMODEL + hcol + c * 8;
        cp16(qhib + off, Qhi + g);
        cp16(qlob + off, Qlo + g);
    }
    CP_COMMIT();

    // prefetch KV tile 0
    {
        const uint32_t stb = stgb;
#pragma unroll
        for (int j = 0; j < 4; j++) {
            const int idx = j * 128 + tid;
            const int r = idx >> 3, c = idx & 7;
            const uint32_t off = (uint32_t)r * 128 + ((uint32_t)c ^ (uint32_t)(r & 7)) * 16;
            const size_t g = (size_t)r * DMODEL + hcol + c * 8;
            cp16(stb + off,                  Khi + g);
            cp16(stb + ATT_TILE_B + off,     Klo + g);
            cp16(stb + 2 * ATT_TILE_B + off, Vhi + g);
            cp16(stb + 3 * ATT_TILE_B + off, Vlo + g);
        }
    }
    CP_COMMIT();

    CP_WAIT1();
    __syncthreads();

    uint32_t qh[2][4][4], ql[2][4][4];
    const uint32_t qrb = (uint32_t)(wid * 32) * 128;
#pragma unroll
    for (int mf = 0; mf < 2; mf++)
#pragma unroll
        for (int ks = 0; ks < 4; ks++) {
            ldsm4(qh[mf][ks], qhib + qrb + mf * 2048 + qoff[ks]);
            ldsm4(ql[mf][ks], qlob + qrb + mf * 2048 + qoff[ks]);
        }

    float O[2][8][4];
#pragma unroll
    for (int mf = 0; mf < 2; mf++)
#pragma unroll
        for (int f = 0; f < 8; f++)
#pragma unroll
            for (int q = 0; q < 4; q++) O[mf][f][q] = 0.f;
    float l0[2] = {0.f, 0.f}, l1[2] = {0.f, 0.f};

    int r0g[2], r1g[2];
#pragma unroll
    for (int mf = 0; mf < 2; mf++) {
        r0g[mf] = q0 + wid * 32 + mf * 16 + (lane >> 2);
        r1g[mf] = r0g[mf] + 8;
    }
    const int wrow_min = q0 + wid * 32;
    const int wrow_max = wrow_min + 31;

    for (int t = 0; t < ntiles; t++) {
        const int s = t & 1;
        if (t + 1 < ntiles) {
            const uint32_t stb = stgb + (s ^ 1) * ATT_STAGE_B;
            const int kn0 = (t + 1) * 64;
#pragma unroll
            for (int j = 0; j < 4; j++) {
                const int idx = j * 128 + tid;
                const int r = idx >> 3, c = idx & 7;
                const uint32_t off = (uint32_t)r * 128 + ((uint32_t)c ^ (uint32_t)(r & 7)) * 16;
                const size_t g = (size_t)(kn0 + r) * DMODEL + hcol + c * 8;
                cp16(stb + off,                  Khi + g);
                cp16(stb + ATT_TILE_B + off,     Klo + g);
                cp16(stb + 2 * ATT_TILE_B + off, Vhi + g);
                cp16(stb + 3 * ATT_TILE_B + off, Vlo + g);
            }
            CP_COMMIT();
            CP_WAIT1();
        } else {
            CP_WAIT0();
        }
        __syncthreads();

        const int k0 = t * 64;
        if (wrow_max >= k0) {
            const bool nomask = (k0 + 63) <= wrow_min;
            const uint32_t stb = stgb + s * ATT_STAGE_B;

#pragma unroll
            for (int np = 0; np < 4; np++) {
                float s8[2][8];
#pragma unroll
                for (int mf = 0; mf < 2; mf++)
#pragma unroll
                    for (int e = 0; e < 8; e++) s8[mf][e] = 0.f;
#pragma unroll
                for (int ks = 0; ks < 4; ks++) {
                    uint32_t kh[4], kl[4];
                    const uint32_t ka = stb + (uint32_t)np * 2048 + koff[ks];
                    ldsm4(kh, ka);
                    ldsm4(kl, ka + ATT_TILE_B);
#pragma unroll
                    for (int mf = 0; mf < 2; mf++) {
                        mma_bf16(&s8[mf][0], qh[mf][ks], kh[0], kh[1]);
                        mma_bf16(&s8[mf][0], qh[mf][ks], kl[0], kl[1]);
                        mma_bf16(&s8[mf][0], ql[mf][ks], kh[0], kh[1]);
                        mma_bf16(&s8[mf][4], qh[mf][ks], kh[2], kh[3]);
                        mma_bf16(&s8[mf][4], qh[mf][ks], kl[2], kl[3]);
                        mma_bf16(&s8[mf][4], ql[mf][ks], kh[2], kh[3]);
                    }
                }

                const int c0 = k0 + np * 16 + ((lane & 3) << 1);
                uint32_t Ph[2][4], Pl[2][4];
#pragma unroll
                for (int mf = 0; mf < 2; mf++) {
                    float p[8];
                    if (nomask) {
#pragma unroll
                        for (int e = 0; e < 8; e++) p[e] = __expf(s8[mf][e]);
                    } else {
                        p[0] = (c0     <= r0g[mf]) ? __expf(s8[mf][0]) : 0.f;
                        p[1] = (c0 + 1 <= r0g[mf]) ? __expf(s8[mf][1]) : 0.f;
                        p[2] = (c0     <= r1g[mf]) ? __expf(s8[mf][2]) : 0.f;
                        p[3] = (c0 + 1 <= r1g[mf]) ? __expf(s8[mf][3]) : 0.f;
                        p[4] = (c0 + 8 <= r0g[mf]) ? __expf(s8[mf][4]) : 0.f;
                        p[5] = (c0 + 9 <= r0g[mf]) ? __expf(s8[mf][5]) : 0.f;
                        p[6] = (c0 + 8 <= r1g[mf]) ? __expf(s8[mf][6]) : 0.f;
                        p[7] = (c0 + 9 <= r1g[mf]) ? __expf(s8[mf][7]) : 0.f;
                    }
                    l0[mf] += (p[0] + p[1]) + (p[4] + p[5]);
                    l1[mf] += (p[2] + p[3]) + (p[6] + p[7]);
#pragma unroll
                    for (int j = 0; j < 4; j++)
                        split2(p[2 * j], p[2 * j + 1], Ph[mf][j], Pl[mf][j]);
                }

#pragma unroll
                for (int dn = 0; dn < 4; dn++) {
                    uint32_t vh[4], vl[4];
                    const uint32_t va = stb + (uint32_t)np * 2048 + voff[dn];
                    ldsm4t(vh, va + 2 * ATT_TILE_B);
                    ldsm4t(vl, va + 3 * ATT_TILE_B);
#pragma unroll
                    for (int mf = 0; mf < 2; mf++) {
                        mma_bf16(O[mf][dn * 2],     Ph[mf], vh[0], vh[1]);
                        mma_bf16(O[mf][dn * 2 + 1], Ph[mf], vh[2], vh[3]);
                        mma_bf16(O[mf][dn * 2],     Ph[mf], vl[0], vl[1]);
                        mma_bf16(O[mf][dn * 2 + 1], Ph[mf], vl[2], vl[3]);
                        mma_bf16(O[mf][dn * 2],     Pl[mf], vh[0], vh[1]);
                        mma_bf16(O[mf][dn * 2 + 1], Pl[mf], vh[2], vh[3]);
                    }
                }
            }
        }
        __syncthreads();
    }

    const int cbase = hcol + ((lane & 3) << 1);
#pragma unroll
    for (int mf = 0; mf < 2; mf++) {
        float a0 = l0[mf], a1 = l1[mf];
        a0 += __shfl_xor_sync(0xFFFFFFFF, a0, 1);
        a0 += __shfl_xor_sync(0xFFFFFFFF, a0, 2);
        a1 += __shfl_xor_sync(0xFFFFFFFF, a1, 1);
        a1 += __shfl_xor_sync(0xFFFFFFFF, a1, 2);
        const float inv0 = 1.f / a0, inv1 = 1.f / a1;
#pragma unroll
        for (int f = 0; f < 8; f++) {
            const size_t o0 = (size_t)r0g[mf] * DMODEL + cbase + f * 8;
            const size_t o1 = (size_t)r1g[mf] * DMODEL + cbase + f * 8;
            uint32_t hh, ll;
            split2(O[mf][f][0] * inv0, O[mf][f][1] * inv0, hh, ll);
            *(uint32_t*)&Chi[o0] = hh; *(uint32_t*)&Clo[o0] = ll;
            split2(O[mf][f][2] * inv1, O[mf][f][3] * inv1, hh, ll);
            *(uint32_t*)&Chi[o1] = hh; *(uint32_t*)&Clo[o1] = ll;
        }
    }
}

// ---------------------------------------------------------------------------
extern "C" void kernel_launch(void* const* d_in, const int* in_sizes, int n_in,
                              void* d_out, int out_size)
{
    const float* x  = (const float*)d_in[0];
    const float* Wq = (const float*)d_in[1];
    const float* Wk = (const float*)d_in[2];
    const float* Wv = (const float*)d_in[3];
    const float* Wo = (const float*)d_in[4];
    float* out = (float*)d_out;

    float *Qp, *Kp;
    cudaGetSymbolAddress((void**)&Qp, g_Q);
    cudaGetSymbolAddress((void**)&Kp, g_K);

    __nv_bfloat16 *xhi, *xlo, *whi, *wlo, *chi, *clo;
    cudaGetSymbolAddress((void**)&xhi, g_xhi);
    cudaGetSymbolAddress((void**)&xlo, g_xlo);
    cudaGetSymbolAddress((void**)&whi, g_whi);
    cudaGetSymbolAddress((void**)&wlo, g_wlo);
    cudaGetSymbolAddress((void**)&chi, g_chi);
    cudaGetSymbolAddress((void**)&clo, g_clo);

    __nv_bfloat16 *qhi, *qlo, *khi, *klo, *vhi, *vlo;
    cudaGetSymbolAddress((void**)&qhi, g_qhi);
    cudaGetSymbolAddress((void**)&qlo, g_qlo);
    cudaGetSymbolAddress((void**)&khi, g_khi);
    cudaGetSymbolAddress((void**)&klo, g_klo);
    cudaGetSymbolAddress((void**)&vhi, g_vhi);
    cudaGetSymbolAddress((void**)&vlo, g_vlo);

    const int WSZ = DMODEL * DMODEL;

    static int attr_set = 0;
    if (!attr_set) {
        cudaFuncSetAttribute(gemm_qkv, cudaFuncAttributeMaxDynamicSharedMemorySize,
                             2 * STAGE_B);
        cudaFuncSetAttribute(gemm_tc, cudaFuncAttributeMaxDynamicSharedMemorySize,
                             2 * STAGE_B);
        cudaFuncSetAttribute(attn_tc, cudaFuncAttributeMaxDynamicSharedMemorySize,
                             ATT_SMEM);
        attr_set = 1;
    }

    split_kernel<<<(SEQ * DMODEL / 4 + 255) / 256, 256>>>(x, xhi, xlo, SEQ * DMODEL / 4);
    split_w4<<<dim3((WSZ / 4 + 255) / 256, 4), 256>>>(Wq, Wk, Wv, Wo, whi, wlo);

    gemm_qkv<<<dim3(DMODEL / 128, SEQ / 128, 3), 128, 2 * STAGE_B>>>(
        xhi, xlo, whi, wlo, Qp, Kp, vhi, vlo);

    rope_conv<<<(SEQ * DMODEL / 4 + 255) / 256, 256>>>(Qp, Kp, qhi, qlo, khi, klo);

    attn_tc<<<dim3(32, NHEAD), 128, ATT_SMEM>>>(qhi, qlo, khi, klo, vhi, vlo, chi, clo);

    gemm_tc<<<dim3(DMODEL / 128, SEQ / 128), 128, 2 * STAGE_B>>>(
        chi, clo, whi + 3 * (size_t)WSZ, wlo + 3 * (size_t)WSZ, out);
}

// round 10
// speedup vs baseline: 1.1200x; 1.1200x over previous
#include <cuda_runtime.h>
#include <cuda_bf16.h>
#include <math.h>
#include <cstdint>

#define SEQ 4096
#define DMODEL 1024
#define NHEAD 16
#define DK 64

// ---------------------------------------------------------------------------
// Scratch (device globals — no runtime allocation allowed)
// ---------------------------------------------------------------------------
__device__ __align__(16) float g_Q[SEQ * DMODEL];
__device__ __align__(16) float g_K[SEQ * DMODEL];

__device__ __align__(16) __nv_bfloat16 g_xhi[SEQ * DMODEL];
__device__ __align__(16) __nv_bfloat16 g_xlo[SEQ * DMODEL];
__device__ __align__(16) __nv_bfloat16 g_whi[4 * DMODEL * DMODEL];
__device__ __align__(16) __nv_bfloat16 g_wlo[4 * DMODEL * DMODEL];
__device__ __align__(16) __nv_bfloat16 g_chi[SEQ * DMODEL];
__device__ __align__(16) __nv_bfloat16 g_clo[SEQ * DMODEL];

__device__ __align__(16) __nv_bfloat16 g_qhi[SEQ * DMODEL];
__device__ __align__(16) __nv_bfloat16 g_qlo[SEQ * DMODEL];
__device__ __align__(16) __nv_bfloat16 g_khi[SEQ * DMODEL];
__device__ __align__(16) __nv_bfloat16 g_klo[SEQ * DMODEL];
__device__ __align__(16) __nv_bfloat16 g_vhi[SEQ * DMODEL];
__device__ __align__(16) __nv_bfloat16 g_vlo[SEQ * DMODEL];

// ---------------------------------------------------------------------------
// Baseline-PTX helpers
// ---------------------------------------------------------------------------
__device__ __forceinline__ uint32_t smem_u32(const void* p) {
    uint32_t a;
    asm("{ .reg .u64 t; cvta.to.shared.u64 t, %1; cvt.u32.u64 %0, t; }"
        : "=r"(a) : "l"(p));
    return a;
}

__device__ __forceinline__ void cp16(uint32_t dst, const void* src) {
    asm volatile("cp.async.cg.shared.global [%0], [%1], 16;"
        :: "r"(dst), "l"(src) : "memory");
}
#define CP_COMMIT() asm volatile("cp.async.commit_group;" ::: "memory")
#define CP_WAIT1()  asm volatile("cp.async.wait_group 1;" ::: "memory")
#define CP_WAIT0()  asm volatile("cp.async.wait_group 0;" ::: "memory")

__device__ __forceinline__ void ldsm4(uint32_t r[4], uint32_t addr) {
    asm volatile("ldmatrix.sync.aligned.m8n8.x4.shared.b16 {%0,%1,%2,%3}, [%4];"
        : "=r"(r[0]), "=r"(r[1]), "=r"(r[2]), "=r"(r[3]) : "r"(addr));
}
__device__ __forceinline__ void ldsm4t(uint32_t r[4], uint32_t addr) {
    asm volatile("ldmatrix.sync.aligned.m8n8.x4.trans.shared.b16 {%0,%1,%2,%3}, [%4];"
        : "=r"(r[0]), "=r"(r[1]), "=r"(r[2]), "=r"(r[3]) : "r"(addr));
}

__device__ __forceinline__ void mma_bf16(float c[4], const uint32_t a[4],
                                         uint32_t b0, uint32_t b1) {
    asm volatile(
        "mma.sync.aligned.m16n8k16.row.col.f32.bf16.bf16.f32 "
        "{%0,%1,%2,%3}, {%4,%5,%6,%7}, {%8,%9}, {%0,%1,%2,%3};"
        : "+f"(c[0]), "+f"(c[1]), "+f"(c[2]), "+f"(c[3])
        : "r"(a[0]), "r"(a[1]), "r"(a[2]), "r"(a[3]), "r"(b0), "r"(b1));
}

__device__ __forceinline__ void split2(float a, float b, uint32_t& hi, uint32_t& lo) {
    __nv_bfloat16 ha = __float2bfloat16(a);
    __nv_bfloat16 hb = __float2bfloat16(b);
    __nv_bfloat162 hp(ha, hb);
    __nv_bfloat162 lp(__float2bfloat16(a - __bfloat162float(ha)),
                      __float2bfloat16(b - __bfloat162float(hb)));
    hi = *(uint32_t*)&hp;
    lo = *(uint32_t*)&lp;
}

// ---------------------------------------------------------------------------
// Elementwise kernels
// ---------------------------------------------------------------------------
__global__ void split_kernel(const float* __restrict__ in,
                             __nv_bfloat16* __restrict__ hi,
                             __nv_bfloat16* __restrict__ lo, int n4)
{
    int i = blockIdx.x * blockDim.x + threadIdx.x;
    if (i >= n4) return;
    float4 v = ((const float4*)in)[i];
    uint32_t h0, l0, h1, l1;
    split2(v.x, v.y, h0, l0);
    split2(v.z, v.w, h1, l1);
    ((uint2*)hi)[i] = make_uint2(h0, h1);
    ((uint2*)lo)[i] = make_uint2(l0, l1);
}

__global__ void split_w4(const float* __restrict__ w0, const float* __restrict__ w1,
                         const float* __restrict__ w2, const float* __restrict__ w3,
                         __nv_bfloat16* __restrict__ hi, __nv_bfloat16* __restrict__ lo)
{
    const int wsel = blockIdx.y;
    const float* src = (wsel == 0) ? w0 : (wsel == 1) ? w1 : (wsel == 2) ? w2 : w3;
    const int n4 = DMODEL * DMODEL / 4;
    int i = blockIdx.x * blockDim.x + threadIdx.x;
    if (i >= n4) return;
    float4 v = ((const float4*)src)[i];
    uint32_t h0, l0, h1, l1;
    split2(v.x, v.y, h0, l0);
    split2(v.z, v.w, h1, l1);
    const size_t base = (size_t)wsel * DMODEL * DMODEL / 4;
    ((uint2*)hi)[base + i] = make_uint2(h0, h1);
    ((uint2*)lo)[base + i] = make_uint2(l0, l1);
}

__global__ void rope_conv(const float* __restrict__ Q, const float* __restrict__ K,
                          __nv_bfloat16* __restrict__ qhi, __nv_bfloat16* __restrict__ qlo,
                          __nv_bfloat16* __restrict__ khi, __nv_bfloat16* __restrict__ klo)
{
    const int n4 = SEQ * DMODEL / 4;
    int idx = blockIdx.x * blockDim.x + threadIdx.x;
    if (idx >= n4) return;

    const int s   = idx >> 8;
    const int f   = idx & 255;
    const int col = f * 4;
    const int i0  = (col & 63) >> 1;

    const float c1 = -9.210340371976184f / 32.0f;
    const float a0 = (float)s * expf((float)i0 * c1);
    const float a1 = (float)s * expf((float)(i0 + 1) * c1);
    float sn0, cs0, sn1, cs1;
    sincosf(a0, &sn0, &cs0);
    sincosf(a1, &sn1, &cs1);

    float4 q = ((const float4*)Q)[idx];
    float4 k = ((const float4*)K)[idx];

    float qx = (q.x * cs0 - q.y * sn0) * 0.125f;
    float qy = (q.x * sn0 + q.y * cs0) * 0.125f;
    float qz = (q.z * cs1 - q.w * sn1) * 0.125f;
    float qw = (q.z * sn1 + q.w * cs1) * 0.125f;
    float kx = k.x * cs0 - k.y * sn0;
    float ky = k.x * sn0 + k.y * cs0;
    float kz = k.z * cs1 - k.w * sn1;
    float kw = k.z * sn1 + k.w * cs1;

    uint32_t h0, l0, h1, l1;
    split2(qx, qy, h0, l0); split2(qz, qw, h1, l1);
    ((uint2*)qhi)[idx] = make_uint2(h0, h1);
    ((uint2*)qlo)[idx] = make_uint2(l0, l1);
    split2(kx, ky, h0, l0); split2(kz, kw, h1, l1);
    ((uint2*)khi)[idx] = make_uint2(h0, h1);
    ((uint2*)klo)[idx] = make_uint2(l0, l1);
}

// ---------------------------------------------------------------------------
// Tensor-core GEMM: 128x128 CTA tile, 4 warps (2x2), 64x64 warp tile.
// BK=32, TWO-stage cp.async pipeline. hi/lo split, fp32 accum.
// ---------------------------------------------------------------------------
#define BK 32
#define NT (DMODEL / BK)
#define TILE_B (128 * 64)           // 8 KB per operand tile
#define STAGE_B (4 * TILE_B)        // 32 KB

struct GemmCore {
    float acc[4][8][4];
    int r0, c0;
};

__device__ __forceinline__ void gemm_mainloop(
    const __nv_bfloat16* __restrict__ Ahi, const __nv_bfloat16* __restrict__ Alo,
    const __nv_bfloat16* __restrict__ Bhi, const __nv_bfloat16* __restrict__ Blo,
    int bm, int bn, char* smem, GemmCore& core)
{
    const int tid  = threadIdx.x;
    const int wid  = tid >> 5, lane = tid & 31;
    const int wm   = wid & 1;
    const int wn   = wid >> 1;
    const uint32_t sbase = smem_u32(smem);

    const __nv_bfloat16* srcs[4] = {
        Ahi + (size_t)bm * DMODEL, Alo + (size_t)bm * DMODEL,
        Bhi + (size_t)bn * DMODEL, Blo + (size_t)bn * DMODEL };

    auto copy_stage = [&](int s, int k0) {
        const uint32_t stb = sbase + s * STAGE_B;
#pragma unroll
        for (int t = 0; t < 4; t++) {
            const __nv_bfloat16* base = srcs[t];
#pragma unroll
            for (int j = 0; j < 4; j++) {
                const int idx = j * 128 + tid;
                const int r = idx >> 2, c = idx & 3;
                const uint32_t pc = (uint32_t)(c ^ ((r >> 1) & 3));
                cp16(stb + t * TILE_B + (uint32_t)r * 64 + pc * 16,
                     base + (size_t)r * DMODEL + k0 + c * 8);
            }
        }
    };

    const int arow = wm * 64 + (lane & 15);
    const int ac0  = lane >> 4;
    const uint32_t aoff = (uint32_t)arow * 64 +
                          (uint32_t)((ac0 ^ ((arow >> 1) & 3)) * 16);
    const int brow = wn * 64 + ((lane >> 4) << 3) + (lane & 7);
    const int bc0  = (lane >> 3) & 1;
    const uint32_t boff = (uint32_t)brow * 64 +
                          (uint32_t)((bc0 ^ ((brow >> 1) & 3)) * 16);

#pragma unroll
    for (int i = 0; i < 4; i++)
#pragma unroll
        for (int j = 0; j < 8; j++)
#pragma unroll
            for (int q = 0; q < 4; q++) core.acc[i][j][q] = 0.f;

    copy_stage(0, 0);
    CP_COMMIT();

    for (int kt = 0; kt < NT; kt++) {
        const int s = kt & 1;
        if (kt + 1 < NT) {
            copy_stage(s ^ 1, (kt + 1) * BK);
            CP_COMMIT();
            CP_WAIT1();
        } else {
            CP_WAIT0();
        }
        __syncthreads();

        const uint32_t stb  = sbase + s * STAGE_B;
        const uint32_t sAhi = stb + aoff;
        const uint32_t sAlo = stb + TILE_B + aoff;
        const uint32_t sBhi = stb + 2 * TILE_B + boff;
        const uint32_t sBlo = stb + 3 * TILE_B + boff;

#pragma unroll
        for (int ks = 0; ks < 2; ks++) {
            const uint32_t kx = (uint32_t)(ks << 5);
            uint32_t ah[4][4], al[4][4], bh[4][4], bl[4][4];
#pragma unroll
            for (int mf = 0; mf < 4; mf++) {
                ldsm4(ah[mf], (sAhi + mf * 1024) ^ kx);
                ldsm4(al[mf], (sAlo + mf * 1024) ^ kx);
            }
#pragma unroll
            for (int np = 0; np < 4; np++) {
                ldsm4(bh[np], (sBhi + np * 1024) ^ kx);
                ldsm4(bl[np], (sBlo + np * 1024) ^ kx);
            }
#pragma unroll
            for (int mf = 0; mf < 4; mf++) {
#pragma unroll
                for (int nt = 0; nt < 8; nt++) {
                    const int np = nt >> 1, hh = (nt & 1) * 2;
                    mma_bf16(core.acc[mf][nt], ah[mf], bh[np][hh], bh[np][hh + 1]);
                    mma_bf16(core.acc[mf][nt], ah[mf], bl[np][hh], bl[np][hh + 1]);
                    mma_bf16(core.acc[mf][nt], al[mf], bh[np][hh], bh[np][hh + 1]);
                }
            }
        }
        __syncthreads();
    }

    core.r0 = bm + wm * 64 + (lane >> 2);
    core.c0 = bn + wn * 64 + (lane & 3) * 2;
}

__global__ __launch_bounds__(128, 2) void gemm_qkv(
    const __nv_bfloat16* __restrict__ Xhi, const __nv_bfloat16* __restrict__ Xlo,
    const __nv_bfloat16* __restrict__ Whi, const __nv_bfloat16* __restrict__ Wlo,
    float* __restrict__ Qout, float* __restrict__ Kout,
    __nv_bfloat16* __restrict__ Vhi, __nv_bfloat16* __restrict__ Vlo)
{
    extern __shared__ __align__(1024) char smem[];
    const int z = blockIdx.z;
    const size_t woff = (size_t)z * DMODEL * DMODEL;

    GemmCore core;
    gemm_mainloop(Xhi, Xlo, Whi + woff, Wlo + woff,
                  blockIdx.y * 128, blockIdx.x * 128, smem, core);

    if (z < 2) {
        float* C = (z == 0) ? Qout : Kout;
#pragma unroll
        for (int mf = 0; mf < 4; mf++) {
#pragma unroll
            for (int nt = 0; nt < 8; nt++) {
                float* p0 = &C[(size_t)(core.r0 + mf * 16) * DMODEL + core.c0 + nt * 8];
                float* p1 = &C[(size_t)(core.r0 + mf * 16 + 8) * DMODEL + core.c0 + nt * 8];
                *(float2*)p0 = make_float2(core.acc[mf][nt][0], core.acc[mf][nt][1]);
                *(float2*)p1 = make_float2(core.acc[mf][nt][2], core.acc[mf][nt][3]);
            }
        }
    } else {
#pragma unroll
        for (int mf = 0; mf < 4; mf++) {
#pragma unroll
            for (int nt = 0; nt < 8; nt++) {
                const size_t o0 = (size_t)(core.r0 + mf * 16) * DMODEL + core.c0 + nt * 8;
                const size_t o1 = (size_t)(core.r0 + mf * 16 + 8) * DMODEL + core.c0 + nt * 8;
                uint32_t h, l;
                split2(core.acc[mf][nt][0], core.acc[mf][nt][1], h, l);
                *(uint32_t*)&Vhi[o0] = h; *(uint32_t*)&Vlo[o0] = l;
                split2(core.acc[mf][nt][2], core.acc[mf][nt][3], h, l);
                *(uint32_t*)&Vhi[o1] = h; *(uint32_t*)&Vlo[o1] = l;
            }
        }
    }
}

__global__ __launch_bounds__(128, 2) void gemm_tc(
    const __nv_bfloat16* __restrict__ Ahi, const __nv_bfloat16* __restrict__ Alo,
    const __nv_bfloat16* __restrict__ Bhi, const __nv_bfloat16* __restrict__ Blo,
    float* __restrict__ C)
{
    extern __shared__ __align__(1024) char smem[];
    GemmCore core;
    gemm_mainloop(Ahi, Alo, Bhi, Blo, blockIdx.y * 128, blockIdx.x * 128, smem, core);
#pragma unroll
    for (int mf = 0; mf < 4; mf++) {
#pragma unroll
        for (int nt = 0; nt < 8; nt++) {
            float* p0 = &C[(size_t)(core.r0 + mf * 16) * DMODEL + core.c0 + nt * 8];
            float* p1 = &C[(size_t)(core.r0 + mf * 16 + 8) * DMODEL + core.c0 + nt * 8];
            *(float2*)p0 = make_float2(core.acc[mf][nt][0], core.acc[mf][nt][1]);
            *(float2*)p1 = make_float2(core.acc[mf][nt][2], core.acc[mf][nt][3]);
        }
    }
}

// ---------------------------------------------------------------------------
// Tensor-core causal flash attention, full hi/lo split numerics.
// 128 threads, 4 warps x 32 q-rows; paired q-tiles (bx, 31-bx) per CTA.
// NEW: per-warp np-chunk skip — 16-key chunks entirely above this warp's
// causal diagonal are skipped (their P would be exactly 0; bit-identical).
// ---------------------------------------------------------------------------
#define ATT_TILE_B 8192
#define ATT_STAGE_B (4 * ATT_TILE_B)
#define ATT_SMEM (32768 + 2 * ATT_STAGE_B)   // 96 KB

__global__ __launch_bounds__(128, 2) void attn_tc(
    const __nv_bfloat16* __restrict__ Qhi, const __nv_bfloat16* __restrict__ Qlo,
    const __nv_bfloat16* __restrict__ Khi, const __nv_bfloat16* __restrict__ Klo,
    const __nv_bfloat16* __restrict__ Vhi, const __nv_bfloat16* __restrict__ Vlo,
    __nv_bfloat16* __restrict__ Chi, __nv_bfloat16* __restrict__ Clo)
{
    extern __shared__ __align__(1024) char smem[];
    const uint32_t sb = smem_u32(smem);
    const uint32_t qhib = sb, qlob = sb + 16384;
    const uint32_t stgb = sb + 32768;

    const int h    = blockIdx.y;
    const int tid  = threadIdx.x;
    const int wid  = tid >> 5, lane = tid & 31;
    const int hcol = h * DK;

    const uint32_t lx = (uint32_t)(lane & 7);
    uint32_t qoff[4], koff[4], voff[4];
#pragma unroll
    for (int ks = 0; ks < 4; ks++) {
        qoff[ks] = (uint32_t)(lane & 15) * 128 +
                   ((uint32_t)(ks * 2 + (lane >> 4)) ^ lx) * 16;
        koff[ks] = (uint32_t)(((lane >> 4) << 3) + (lane & 7)) * 128 +
                   ((uint32_t)(ks * 2 + ((lane >> 3) & 1)) ^ lx) * 16;
        voff[ks] = (uint32_t)(lane & 15) * 128 +
                   ((uint32_t)(ks * 2 + (lane >> 4)) ^ lx) * 16;
    }

#pragma unroll 1
    for (int rep = 0; rep < 2; rep++) {
        const int qtile = (rep == 0) ? blockIdx.x : (31 - blockIdx.x);
        const int q0 = qtile * 128;
        const int ntiles = qtile * 2 + 2;

        __syncthreads();

#pragma unroll
        for (int j = 0; j < 8; j++) {
            const int idx = j * 128 + tid;
            const int r = idx >> 3, c = idx & 7;
            const uint32_t off = (uint32_t)r * 128 + ((uint32_t)c ^ (uint32_t)(r & 7)) * 16;
            const size_t g = (size_t)(q0 + r) * DMODEL + hcol + c * 8;
            cp16(qhib + off, Qhi + g);
            cp16(qlob + off, Qlo + g);
        }
        CP_COMMIT();

        {
            const uint32_t stb = stgb;
#pragma unroll
            for (int j = 0; j < 4; j++) {
                const int idx = j * 128 + tid;
                const int r = idx >> 3, c = idx & 7;
                const uint32_t off = (uint32_t)r * 128 + ((uint32_t)c ^ (uint32_t)(r & 7)) * 16;
                const size_t g = (size_t)r * DMODEL + hcol + c * 8;
                cp16(stb + off,                  Khi + g);
                cp16(stb + ATT_TILE_B + off,     Klo + g);
                cp16(stb + 2 * ATT_TILE_B + off, Vhi + g);
                cp16(stb + 3 * ATT_TILE_B + off, Vlo + g);
            }
        }
        CP_COMMIT();

        CP_WAIT1();
        __syncthreads();

        uint32_t qh[2][4][4], ql[2][4][4];
        const uint32_t qrb = (uint32_t)(wid * 32) * 128;
#pragma unroll
        for (int mf = 0; mf < 2; mf++)
#pragma unroll
            for (int ks = 0; ks < 4; ks++) {
                ldsm4(qh[mf][ks], qhib + qrb + mf * 2048 + qoff[ks]);
                ldsm4(ql[mf][ks], qlob + qrb + mf * 2048 + qoff[ks]);
            }

        float O[2][8][4];
#pragma unroll
        for (int mf = 0; mf < 2; mf++)
#pragma unroll
            for (int f = 0; f < 8; f++)
#pragma unroll
                for (int q = 0; q < 4; q++) O[mf][f][q] = 0.f;
        float l0[2] = {0.f, 0.f}, l1[2] = {0.f, 0.f};

        int r0g[2], r1g[2];
#pragma unroll
        for (int mf = 0; mf < 2; mf++) {
            r0g[mf] = q0 + wid * 32 + mf * 16 + (lane >> 2);
            r1g[mf] = r0g[mf] + 8;
        }
        const int wrow_min = q0 + wid * 32;
        const int wrow_max = wrow_min + 31;

        for (int t = 0; t < ntiles; t++) {
            const int s = t & 1;
            if (t + 1 < ntiles) {
                const uint32_t stb = stgb + (s ^ 1) * ATT_STAGE_B;
                const int kn0 = (t + 1) * 64;
#pragma unroll
                for (int j = 0; j < 4; j++) {
                    const int idx = j * 128 + tid;
                    const int r = idx >> 3, c = idx & 7;
                    const uint32_t off = (uint32_t)r * 128 + ((uint32_t)c ^ (uint32_t)(r & 7)) * 16;
                    const size_t g = (size_t)(kn0 + r) * DMODEL + hcol + c * 8;
                    cp16(stb + off,                  Khi + g);
                    cp16(stb + ATT_TILE_B + off,     Klo + g);
                    cp16(stb + 2 * ATT_TILE_B + off, Vhi + g);
                    cp16(stb + 3 * ATT_TILE_B + off, Vlo + g);
                }
                CP_COMMIT();
                CP_WAIT1();
            } else {
                CP_WAIT0();
            }
            __syncthreads();

            const int k0 = t * 64;
            if (wrow_max >= k0) {
                const bool nomask = (k0 + 63) <= wrow_min;
                const uint32_t stb = stgb + s * ATT_STAGE_B;

#pragma unroll
                for (int np = 0; np < 4; np++) {
                    // skip 16-key chunks entirely above this warp's diagonal:
                    // every P element would be exactly 0 (bit-identical skip)
                    if (k0 + np * 16 > wrow_max) continue;

                    float s8[2][8];
#pragma unroll
                    for (int mf = 0; mf < 2; mf++)
#pragma unroll
                        for (int e = 0; e < 8; e++) s8[mf][e] = 0.f;
#pragma unroll
                    for (int ks = 0; ks < 4; ks++) {
                        uint32_t kh[4], kl[4];
                        const uint32_t ka = stb + (uint32_t)np * 2048 + koff[ks];
                        ldsm4(kh, ka);
                        ldsm4(kl, ka + ATT_TILE_B);
#pragma unroll
                        for (int mf = 0; mf < 2; mf++) {
                            mma_bf16(&s8[mf][0], qh[mf][ks], kh[0], kh[1]);
                            mma_bf16(&s8[mf][0], qh[mf][ks], kl[0], kl[1]);
                            mma_bf16(&s8[mf][0], ql[mf][ks], kh[0], kh[1]);
                            mma_bf16(&s8[mf][4], qh[mf][ks], kh[2], kh[3]);
                            mma_bf16(&s8[mf][4], qh[mf][ks], kl[2], kl[3]);
                            mma_bf16(&s8[mf][4], ql[mf][ks], kh[2], kh[3]);
                        }
                    }

                    const int c0 = k0 + np * 16 + ((lane & 3) << 1);
                    uint32_t Ph[2][4], Pl[2][4];
#pragma unroll
                    for (int mf = 0; mf < 2; mf++) {
                        float p[8];
                        if (nomask) {
#pragma unroll
                            for (int e = 0; e < 8; e++) p[e] = __expf(s8[mf][e]);
                        } else {
                            p[0] = (c0     <= r0g[mf]) ? __expf(s8[mf][0]) : 0.f;
                            p[1] = (c0 + 1 <= r0g[mf]) ? __expf(s8[mf][1]) : 0.f;
                            p[2] = (c0     <= r1g[mf]) ? __expf(s8[mf][2]) : 0.f;
                            p[3] = (c0 + 1 <= r1g[mf]) ? __expf(s8[mf][3]) : 0.f;
                            p[4] = (c0 + 8 <= r0g[mf]) ? __expf(s8[mf][4]) : 0.f;
                            p[5] = (c0 + 9 <= r0g[mf]) ? __expf(s8[mf][5]) : 0.f;
                            p[6] = (c0 + 8 <= r1g[mf]) ? __expf(s8[mf][6]) : 0.f;
                            p[7] = (c0 + 9 <= r1g[mf]) ? __expf(s8[mf][7]) : 0.f;
                        }
                        l0[mf] += (p[0] + p[1]) + (p[4] + p[5]);
                        l1[mf] += (p[2] + p[3]) + (p[6] + p[7]);
#pragma unroll
                        for (int j = 0; j < 4; j++)
                            split2(p[2 * j], p[2 * j + 1], Ph[mf][j], Pl[mf][j]);
                    }

#pragma unroll
                    for (int dn = 0; dn < 4; dn++) {
                        uint32_t vh[4], vl[4];
                        const uint32_t va = stb + (uint32_t)np * 2048 + voff[dn];
                        ldsm4t(vh, va + 2 * ATT_TILE_B);
                        ldsm4t(vl, va + 3 * ATT_TILE_B);
#pragma unroll
                        for (int mf = 0; mf < 2; mf++) {
                            mma_bf16(O[mf][dn * 2],     Ph[mf], vh[0], vh[1]);
                            mma_bf16(O[mf][dn * 2 + 1], Ph[mf], vh[2], vh[3]);
                            mma_bf16(O[mf][dn * 2],     Ph[mf], vl[0], vl[1]);
                            mma_bf16(O[mf][dn * 2 + 1], Ph[mf], vl[2], vl[3]);
                            mma_bf16(O[mf][dn * 2],     Pl[mf], vh[0], vh[1]);
                            mma_bf16(O[mf][dn * 2 + 1], Pl[mf], vh[2], vh[3]);
                        }
                    }
                }
            }
            __syncthreads();
        }

        const int cbase = hcol + ((lane & 3) << 1);
#pragma unroll
        for (int mf = 0; mf < 2; mf++) {
            float a0 = l0[mf], a1 = l1[mf];
            a0 += __shfl_xor_sync(0xFFFFFFFF, a0, 1);
            a0 += __shfl_xor_sync(0xFFFFFFFF, a0, 2);
            a1 += __shfl_xor_sync(0xFFFFFFFF, a1, 1);
            a1 += __shfl_xor_sync(0xFFFFFFFF, a1, 2);
            const float inv0 = 1.f / a0, inv1 = 1.f / a1;
#pragma unroll
            for (int f = 0; f < 8; f++) {
                const size_t o0 = (size_t)r0g[mf] * DMODEL + cbase + f * 8;
                const size_t o1 = (size_t)r1g[mf] * DMODEL + cbase + f * 8;
                uint32_t hh, ll;
                split2(O[mf][f][0] * inv0, O[mf][f][1] * inv0, hh, ll);
                *(uint32_t*)&Chi[o0] = hh; *(uint32_t*)&Clo[o0] = ll;
                split2(O[mf][f][2] * inv1, O[mf][f][3] * inv1, hh, ll);
                *(uint32_t*)&Chi[o1] = hh; *(uint32_t*)&Clo[o1] = ll;
            }
        }
    }
}

// ---------------------------------------------------------------------------
extern "C" void kernel_launch(void* const* d_in, const int* in_sizes, int n_in,
                              void* d_out, int out_size)
{
    const float* x  = (const float*)d_in[0];
    const float* Wq = (const float*)d_in[1];
    const float* Wk = (const float*)d_in[2];
    const float* Wv = (const float*)d_in[3];
    const float* Wo = (const float*)d_in[4];
    float* out = (float*)d_out;

    float *Qp, *Kp;
    cudaGetSymbolAddress((void**)&Qp, g_Q);
    cudaGetSymbolAddress((void**)&Kp, g_K);

    __nv_bfloat16 *xhi, *xlo, *whi, *wlo, *chi, *clo;
    cudaGetSymbolAddress((void**)&xhi, g_xhi);
    cudaGetSymbolAddress((void**)&xlo, g_xlo);
    cudaGetSymbolAddress((void**)&whi, g_whi);
    cudaGetSymbolAddress((void**)&wlo, g_wlo);
    cudaGetSymbolAddress((void**)&chi, g_chi);
    cudaGetSymbolAddress((void**)&clo, g_clo);

    __nv_bfloat16 *qhi, *qlo, *khi, *klo, *vhi, *vlo;
    cudaGetSymbolAddress((void**)&qhi, g_qhi);
    cudaGetSymbolAddress((void**)&qlo, g_qlo);
    cudaGetSymbolAddress((void**)&khi, g_khi);
    cudaGetSymbolAddress((void**)&klo, g_klo);
    cudaGetSymbolAddress((void**)&vhi, g_vhi);
    cudaGetSymbolAddress((void**)&vlo, g_vlo);

    const int WSZ = DMODEL * DMODEL;

    static int attr_set = 0;
    if (!attr_set) {
        cudaFuncSetAttribute(gemm_qkv, cudaFuncAttributeMaxDynamicSharedMemorySize,
                             2 * STAGE_B);
        cudaFuncSetAttribute(gemm_tc, cudaFuncAttributeMaxDynamicSharedMemorySize,
                             2 * STAGE_B);
        cudaFuncSetAttribute(attn_tc, cudaFuncAttributeMaxDynamicSharedMemorySize,
                             ATT_SMEM);
        attr_set = 1;
    }

    split_kernel<<<(SEQ * DMODEL / 4 + 255) / 256, 256>>>(x, xhi, xlo, SEQ * DMODEL / 4);
    split_w4<<<dim3((WSZ / 4 + 255) / 256, 4), 256>>>(Wq, Wk, Wv, Wo, whi, wlo);

    gemm_qkv<<<dim3(DMODEL / 128, SEQ / 128, 3), 128, 2 * STAGE_B>>>(
        xhi, xlo, whi, wlo, Qp, Kp, vhi, vlo);

    rope_conv<<<(SEQ * DMODEL / 4 + 255) / 256, 256>>>(Qp, Kp, qhi, qlo, khi, klo);

    attn_tc<<<dim3(16, NHEAD), 128, ATT_SMEM>>>(qhi, qlo, khi, klo, vhi, vlo, chi, clo);

    gemm_tc<<<dim3(DMODEL / 128, SEQ / 128), 128, 2 * STAGE_B>>>(
        chi, clo, whi + 3 * (size_t)WSZ, wlo + 3 * (size_t)WSZ, out);
}

// round 11
// speedup vs baseline: 1.1501x; 1.0269x over previous
#include <cuda_runtime.h>
#include <cuda_bf16.h>
#include <math.h>
#include <cstdint>

#define SEQ 4096
#define DMODEL 1024
#define NHEAD 16
#define DK 64

// ---------------------------------------------------------------------------
// Scratch (device globals — no runtime allocation allowed)
// ---------------------------------------------------------------------------
__device__ __align__(16) float g_Q[SEQ * DMODEL];
__device__ __align__(16) float g_K[SEQ * DMODEL];

__device__ __align__(16) __nv_bfloat16 g_xhi[SEQ * DMODEL];
__device__ __align__(16) __nv_bfloat16 g_xlo[SEQ * DMODEL];
__device__ __align__(16) __nv_bfloat16 g_whi[4 * DMODEL * DMODEL];
__device__ __align__(16) __nv_bfloat16 g_wlo[4 * DMODEL * DMODEL];
__device__ __align__(16) __nv_bfloat16 g_chi[SEQ * DMODEL];
__device__ __align__(16) __nv_bfloat16 g_clo[SEQ * DMODEL];

__device__ __align__(16) __nv_bfloat16 g_qhi[SEQ * DMODEL];
__device__ __align__(16) __nv_bfloat16 g_qlo[SEQ * DMODEL];
__device__ __align__(16) __nv_bfloat16 g_khi[SEQ * DMODEL];
__device__ __align__(16) __nv_bfloat16 g_klo[SEQ * DMODEL];
__device__ __align__(16) __nv_bfloat16 g_vhi[SEQ * DMODEL];
__device__ __align__(16) __nv_bfloat16 g_vlo[SEQ * DMODEL];

// work-stealing counter for the persistent attention kernel (reset per launch)
__device__ int g_attn_work;

// ---------------------------------------------------------------------------
// Baseline-PTX helpers
// ---------------------------------------------------------------------------
__device__ __forceinline__ uint32_t smem_u32(const void* p) {
    uint32_t a;
    asm("{ .reg .u64 t; cvta.to.shared.u64 t, %1; cvt.u32.u64 %0, t; }"
        : "=r"(a) : "l"(p));
    return a;
}

__device__ __forceinline__ void cp16(uint32_t dst, const void* src) {
    asm volatile("cp.async.cg.shared.global [%0], [%1], 16;"
        :: "r"(dst), "l"(src) : "memory");
}
#define CP_COMMIT() asm volatile("cp.async.commit_group;" ::: "memory")
#define CP_WAIT1()  asm volatile("cp.async.wait_group 1;" ::: "memory")
#define CP_WAIT0()  asm volatile("cp.async.wait_group 0;" ::: "memory")

__device__ __forceinline__ void ldsm4(uint32_t r[4], uint32_t addr) {
    asm volatile("ldmatrix.sync.aligned.m8n8.x4.shared.b16 {%0,%1,%2,%3}, [%4];"
        : "=r"(r[0]), "=r"(r[1]), "=r"(r[2]), "=r"(r[3]) : "r"(addr));
}
__device__ __forceinline__ void ldsm4t(uint32_t r[4], uint32_t addr) {
    asm volatile("ldmatrix.sync.aligned.m8n8.x4.trans.shared.b16 {%0,%1,%2,%3}, [%4];"
        : "=r"(r[0]), "=r"(r[1]), "=r"(r[2]), "=r"(r[3]) : "r"(addr));
}

__device__ __forceinline__ void mma_bf16(float c[4], const uint32_t a[4],
                                         uint32_t b0, uint32_t b1) {
    asm volatile(
        "mma.sync.aligned.m16n8k16.row.col.f32.bf16.bf16.f32 "
        "{%0,%1,%2,%3}, {%4,%5,%6,%7}, {%8,%9}, {%0,%1,%2,%3};"
        : "+f"(c[0]), "+f"(c[1]), "+f"(c[2]), "+f"(c[3])
        : "r"(a[0]), "r"(a[1]), "r"(a[2]), "r"(a[3]), "r"(b0), "r"(b1));
}

__device__ __forceinline__ void split2(float a, float b, uint32_t& hi, uint32_t& lo) {
    __nv_bfloat16 ha = __float2bfloat16(a);
    __nv_bfloat16 hb = __float2bfloat16(b);
    __nv_bfloat162 hp(ha, hb);
    __nv_bfloat162 lp(__float2bfloat16(a - __bfloat162float(ha)),
                      __float2bfloat16(b - __bfloat162float(hb)));
    hi = *(uint32_t*)&hp;
    lo = *(uint32_t*)&lp;
}

// ---------------------------------------------------------------------------
// Elementwise kernels
// ---------------------------------------------------------------------------
__global__ void split_kernel(const float* __restrict__ in,
                             __nv_bfloat16* __restrict__ hi,
                             __nv_bfloat16* __restrict__ lo, int n4)
{
    int i = blockIdx.x * blockDim.x + threadIdx.x;
    if (i >= n4) return;
    float4 v = ((const float4*)in)[i];
    uint32_t h0, l0, h1, l1;
    split2(v.x, v.y, h0, l0);
    split2(v.z, v.w, h1, l1);
    ((uint2*)hi)[i] = make_uint2(h0, h1);
    ((uint2*)lo)[i] = make_uint2(l0, l1);
}

__global__ void split_w4(const float* __restrict__ w0, const float* __restrict__ w1,
                         const float* __restrict__ w2, const float* __restrict__ w3,
                         __nv_bfloat16* __restrict__ hi, __nv_bfloat16* __restrict__ lo)
{
    const int wsel = blockIdx.y;
    const float* src = (wsel == 0) ? w0 : (wsel == 1) ? w1 : (wsel == 2) ? w2 : w3;
    const int n4 = DMODEL * DMODEL / 4;
    int i = blockIdx.x * blockDim.x + threadIdx.x;
    if (i >= n4) return;
    float4 v = ((const float4*)src)[i];
    uint32_t h0, l0, h1, l1;
    split2(v.x, v.y, h0, l0);
    split2(v.z, v.w, h1, l1);
    const size_t base = (size_t)wsel * DMODEL * DMODEL / 4;
    ((uint2*)hi)[base + i] = make_uint2(h0, h1);
    ((uint2*)lo)[base + i] = make_uint2(l0, l1);
}

__global__ void rope_conv(const float* __restrict__ Q, const float* __restrict__ K,
                          __nv_bfloat16* __restrict__ qhi, __nv_bfloat16* __restrict__ qlo,
                          __nv_bfloat16* __restrict__ khi, __nv_bfloat16* __restrict__ klo)
{
    const int n4 = SEQ * DMODEL / 4;
    int idx = blockIdx.x * blockDim.x + threadIdx.x;
    if (idx >= n4) return;

    const int s   = idx >> 8;
    const int f   = idx & 255;
    const int col = f * 4;
    const int i0  = (col & 63) >> 1;

    const float c1 = -9.210340371976184f / 32.0f;
    const float a0 = (float)s * expf((float)i0 * c1);
    const float a1 = (float)s * expf((float)(i0 + 1) * c1);
    float sn0, cs0, sn1, cs1;
    sincosf(a0, &sn0, &cs0);
    sincosf(a1, &sn1, &cs1);

    float4 q = ((const float4*)Q)[idx];
    float4 k = ((const float4*)K)[idx];

    float qx = (q.x * cs0 - q.y * sn0) * 0.125f;
    float qy = (q.x * sn0 + q.y * cs0) * 0.125f;
    float qz = (q.z * cs1 - q.w * sn1) * 0.125f;
    float qw = (q.z * sn1 + q.w * cs1) * 0.125f;
    float kx = k.x * cs0 - k.y * sn0;
    float ky = k.x * sn0 + k.y * cs0;
    float kz = k.z * cs1 - k.w * sn1;
    float kw = k.z * sn1 + k.w * cs1;

    uint32_t h0, l0, h1, l1;
    split2(qx, qy, h0, l0); split2(qz, qw, h1, l1);
    ((uint2*)qhi)[idx] = make_uint2(h0, h1);
    ((uint2*)qlo)[idx] = make_uint2(l0, l1);
    split2(kx, ky, h0, l0); split2(kz, kw, h1, l1);
    ((uint2*)khi)[idx] = make_uint2(h0, h1);
    ((uint2*)klo)[idx] = make_uint2(l0, l1);
}

// ---------------------------------------------------------------------------
// Tensor-core GEMM: 128x128 CTA tile, 4 warps (2x2), 64x64 warp tile.
// BK=32, TWO-stage cp.async pipeline. hi/lo split, fp32 accum. (568us build)
// ---------------------------------------------------------------------------
#define BK 32
#define NT (DMODEL / BK)
#define TILE_B (128 * 64)           // 8 KB per operand tile
#define STAGE_B (4 * TILE_B)        // 32 KB

struct GemmCore {
    float acc[4][8][4];
    int r0, c0;
};

__device__ __forceinline__ void gemm_mainloop(
    const __nv_bfloat16* __restrict__ Ahi, const __nv_bfloat16* __restrict__ Alo,
    const __nv_bfloat16* __restrict__ Bhi, const __nv_bfloat16* __restrict__ Blo,
    int bm, int bn, char* smem, GemmCore& core)
{
    const int tid  = threadIdx.x;
    const int wid  = tid >> 5, lane = tid & 31;
    const int wm   = wid & 1;
    const int wn   = wid >> 1;
    const uint32_t sbase = smem_u32(smem);

    const __nv_bfloat16* srcs[4] = {
        Ahi + (size_t)bm * DMODEL, Alo + (size_t)bm * DMODEL,
        Bhi + (size_t)bn * DMODEL, Blo + (size_t)bn * DMODEL };

    auto copy_stage = [&](int s, int k0) {
        const uint32_t stb = sbase + s * STAGE_B;
#pragma unroll
        for (int t = 0; t < 4; t++) {
            const __nv_bfloat16* base = srcs[t];
#pragma unroll
            for (int j = 0; j < 4; j++) {
                const int idx = j * 128 + tid;
                const int r = idx >> 2, c = idx & 3;
                const uint32_t pc = (uint32_t)(c ^ ((r >> 1) & 3));
                cp16(stb + t * TILE_B + (uint32_t)r * 64 + pc * 16,
                     base + (size_t)r * DMODEL + k0 + c * 8);
            }
        }
    };

    const int arow = wm * 64 + (lane & 15);
    const int ac0  = lane >> 4;
    const uint32_t aoff = (uint32_t)arow * 64 +
                          (uint32_t)((ac0 ^ ((arow >> 1) & 3)) * 16);
    const int brow = wn * 64 + ((lane >> 4) << 3) + (lane & 7);
    const int bc0  = (lane >> 3) & 1;
    const uint32_t boff = (uint32_t)brow * 64 +
                          (uint32_t)((bc0 ^ ((brow >> 1) & 3)) * 16);

#pragma unroll
    for (int i = 0; i < 4; i++)
#pragma unroll
        for (int j = 0; j < 8; j++)
#pragma unroll
            for (int q = 0; q < 4; q++) core.acc[i][j][q] = 0.f;

    copy_stage(0, 0);
    CP_COMMIT();

    for (int kt = 0; kt < NT; kt++) {
        const int s = kt & 1;
        if (kt + 1 < NT) {
            copy_stage(s ^ 1, (kt + 1) * BK);
            CP_COMMIT();
            CP_WAIT1();
        } else {
            CP_WAIT0();
        }
        __syncthreads();

        const uint32_t stb  = sbase + s * STAGE_B;
        const uint32_t sAhi = stb + aoff;
        const uint32_t sAlo = stb + TILE_B + aoff;
        const uint32_t sBhi = stb + 2 * TILE_B + boff;
        const uint32_t sBlo = stb + 3 * TILE_B + boff;

#pragma unroll
        for (int ks = 0; ks < 2; ks++) {
            const uint32_t kx = (uint32_t)(ks << 5);
            uint32_t ah[4][4], al[4][4], bh[4][4], bl[4][4];
#pragma unroll
            for (int mf = 0; mf < 4; mf++) {
                ldsm4(ah[mf], (sAhi + mf * 1024) ^ kx);
                ldsm4(al[mf], (sAlo + mf * 1024) ^ kx);
            }
#pragma unroll
            for (int np = 0; np < 4; np++) {
                ldsm4(bh[np], (sBhi + np * 1024) ^ kx);
                ldsm4(bl[np], (sBlo + np * 1024) ^ kx);
            }
#pragma unroll
            for (int mf = 0; mf < 4; mf++) {
#pragma unroll
                for (int nt = 0; nt < 8; nt++) {
                    const int np = nt >> 1, hh = (nt & 1) * 2;
                    mma_bf16(core.acc[mf][nt], ah[mf], bh[np][hh], bh[np][hh + 1]);
                    mma_bf16(core.acc[mf][nt], ah[mf], bl[np][hh], bl[np][hh + 1]);
                    mma_bf16(core.acc[mf][nt], al[mf], bh[np][hh], bh[np][hh + 1]);
                }
            }
        }
        __syncthreads();
    }

    core.r0 = bm + wm * 64 + (lane >> 2);
    core.c0 = bn + wn * 64 + (lane & 3) * 2;
}

__global__ __launch_bounds__(128, 2) void gemm_qkv(
    const __nv_bfloat16* __restrict__ Xhi, const __nv_bfloat16* __restrict__ Xlo,
    const __nv_bfloat16* __restrict__ Whi, const __nv_bfloat16* __restrict__ Wlo,
    float* __restrict__ Qout, float* __restrict__ Kout,
    __nv_bfloat16* __restrict__ Vhi, __nv_bfloat16* __restrict__ Vlo)
{
    extern __shared__ __align__(1024) char smem[];
    const int z = blockIdx.z;
    const size_t woff = (size_t)z * DMODEL * DMODEL;

    GemmCore core;
    gemm_mainloop(Xhi, Xlo, Whi + woff, Wlo + woff,
                  blockIdx.y * 128, blockIdx.x * 128, smem, core);

    if (z < 2) {
        float* C = (z == 0) ? Qout : Kout;
#pragma unroll
        for (int mf = 0; mf < 4; mf++) {
#pragma unroll
            for (int nt = 0; nt < 8; nt++) {
                float* p0 = &C[(size_t)(core.r0 + mf * 16) * DMODEL + core.c0 + nt * 8];
                float* p1 = &C[(size_t)(core.r0 + mf * 16 + 8) * DMODEL + core.c0 + nt * 8];
                *(float2*)p0 = make_float2(core.acc[mf][nt][0], core.acc[mf][nt][1]);
                *(float2*)p1 = make_float2(core.acc[mf][nt][2], core.acc[mf][nt][3]);
            }
        }
    } else {
#pragma unroll
        for (int mf = 0; mf < 4; mf++) {
#pragma unroll
            for (int nt = 0; nt < 8; nt++) {
                const size_t o0 = (size_t)(core.r0 + mf * 16) * DMODEL + core.c0 + nt * 8;
                const size_t o1 = (size_t)(core.r0 + mf * 16 + 8) * DMODEL + core.c0 + nt * 8;
                uint32_t h, l;
                split2(core.acc[mf][nt][0], core.acc[mf][nt][1], h, l);
                *(uint32_t*)&Vhi[o0] = h; *(uint32_t*)&Vlo[o0] = l;
                split2(core.acc[mf][nt][2], core.acc[mf][nt][3], h, l);
                *(uint32_t*)&Vhi[o1] = h; *(uint32_t*)&Vlo[o1] = l;
            }
        }
    }
}

__global__ __launch_bounds__(128, 2) void gemm_tc(
    const __nv_bfloat16* __restrict__ Ahi, const __nv_bfloat16* __restrict__ Alo,
    const __nv_bfloat16* __restrict__ Bhi, const __nv_bfloat16* __restrict__ Blo,
    float* __restrict__ C)
{
    extern __shared__ __align__(1024) char smem[];
    GemmCore core;
    gemm_mainloop(Ahi, Alo, Bhi, Blo, blockIdx.y * 128, blockIdx.x * 128, smem, core);
#pragma unroll
    for (int mf = 0; mf < 4; mf++) {
#pragma unroll
        for (int nt = 0; nt < 8; nt++) {
            float* p0 = &C[(size_t)(core.r0 + mf * 16) * DMODEL + core.c0 + nt * 8];
            float* p1 = &C[(size_t)(core.r0 + mf * 16 + 8) * DMODEL + core.c0 + nt * 8];
            *(float2*)p0 = make_float2(core.acc[mf][nt][0], core.acc[mf][nt][1]);
            *(float2*)p1 = make_float2(core.acc[mf][nt][2], core.acc[mf][nt][3]);
        }
    }
}

// ---------------------------------------------------------------------------
// PERSISTENT tensor-core causal flash attention, full hi/lo split numerics.
// 296 persistent CTAs; a global atomic counter hands out the 512
// (q-tile, head) units in LPT order (largest q-tiles first). Work-stealing
// balances SM-level load regardless of CTA placement.
// ---------------------------------------------------------------------------
#define ATT_TILE_B 8192
#define ATT_STAGE_B (4 * ATT_TILE_B)
#define ATT_SMEM (32768 + 2 * ATT_STAGE_B)   // 96 KB
#define ATT_UNITS (32 * NHEAD)               // 512
#define ATT_CTAS 296                         // 2 per SM x 148 SMs

__global__ __launch_bounds__(128, 2) void attn_tc(
    const __nv_bfloat16* __restrict__ Qhi, const __nv_bfloat16* __restrict__ Qlo,
    const __nv_bfloat16* __restrict__ Khi, const __nv_bfloat16* __restrict__ Klo,
    const __nv_bfloat16* __restrict__ Vhi, const __nv_bfloat16* __restrict__ Vlo,
    __nv_bfloat16* __restrict__ Chi, __nv_bfloat16* __restrict__ Clo)
{
    extern __shared__ __align__(1024) char smem[];
    __shared__ int s_unit;
    const uint32_t sb = smem_u32(smem);
    const uint32_t qhib = sb, qlob = sb + 16384;
    const uint32_t stgb = sb + 32768;

    const int tid  = threadIdx.x;
    const int wid  = tid >> 5, lane = tid & 31;

    const uint32_t lx = (uint32_t)(lane & 7);
    uint32_t qoff[4], koff[4], voff[4];
#pragma unroll
    for (int ks = 0; ks < 4; ks++) {
        qoff[ks] = (uint32_t)(lane & 15) * 128 +
                   ((uint32_t)(ks * 2 + (lane >> 4)) ^ lx) * 16;
        koff[ks] = (uint32_t)(((lane >> 4) << 3) + (lane & 7)) * 128 +
                   ((uint32_t)(ks * 2 + ((lane >> 3) & 1)) ^ lx) * 16;
        voff[ks] = (uint32_t)(lane & 15) * 128 +
                   ((uint32_t)(ks * 2 + (lane >> 4)) ^ lx) * 16;
    }

    for (;;) {
        __syncthreads();   // all smem reads of previous unit done; protect s_unit
        if (tid == 0) s_unit = atomicAdd(&g_attn_work, 1);
        __syncthreads();
        const int u = s_unit;
        if (u >= ATT_UNITS) break;

        const int qtile = 31 - (u >> 4);     // LPT: largest tiles first
        const int h     = u & 15;
        const int hcol  = h * DK;
        const int q0 = qtile * 128;
        const int ntiles = qtile * 2 + 2;

        // Q (hi+lo) tile
#pragma unroll
        for (int j = 0; j < 8; j++) {
            const int idx = j * 128 + tid;
            const int r = idx >> 3, c = idx & 7;
            const uint32_t off = (uint32_t)r * 128 + ((uint32_t)c ^ (uint32_t)(r & 7)) * 16;
            const size_t g = (size_t)(q0 + r) * DMODEL + hcol + c * 8;
            cp16(qhib + off, Qhi + g);
            cp16(qlob + off, Qlo + g);
        }
        CP_COMMIT();

        // prefetch KV tile 0
        {
            const uint32_t stb = stgb;
#pragma unroll
            for (int j = 0; j < 4; j++) {
                const int idx = j * 128 + tid;
                const int r = idx >> 3, c = idx & 7;
                const uint32_t off = (uint32_t)r * 128 + ((uint32_t)c ^ (uint32_t)(r & 7)) * 16;
                const size_t g = (size_t)r * DMODEL + hcol + c * 8;
                cp16(stb + off,                  Khi + g);
                cp16(stb + ATT_TILE_B + off,     Klo + g);
                cp16(stb + 2 * ATT_TILE_B + off, Vhi + g);
                cp16(stb + 3 * ATT_TILE_B + off, Vlo + g);
            }
        }
        CP_COMMIT();

        CP_WAIT1();
        __syncthreads();

        uint32_t qh[2][4][4], ql[2][4][4];
        const uint32_t qrb = (uint32_t)(wid * 32) * 128;
#pragma unroll
        for (int mf = 0; mf < 2; mf++)
#pragma unroll
            for (int ks = 0; ks < 4; ks++) {
                ldsm4(qh[mf][ks], qhib + qrb + mf * 2048 + qoff[ks]);
                ldsm4(ql[mf][ks], qlob + qrb + mf * 2048 + qoff[ks]);
            }

        float O[2][8][4];
#pragma unroll
        for (int mf = 0; mf < 2; mf++)
#pragma unroll
            for (int f = 0; f < 8; f++)
#pragma unroll
                for (int q = 0; q < 4; q++) O[mf][f][q] = 0.f;
        float l0[2] = {0.f, 0.f}, l1[2] = {0.f, 0.f};

        int r0g[2], r1g[2];
#pragma unroll
        for (int mf = 0; mf < 2; mf++) {
            r0g[mf] = q0 + wid * 32 + mf * 16 + (lane >> 2);
            r1g[mf] = r0g[mf] + 8;
        }
        const int wrow_min = q0 + wid * 32;
        const int wrow_max = wrow_min + 31;

        for (int t = 0; t < ntiles; t++) {
            const int s = t & 1;
            if (t + 1 < ntiles) {
                const uint32_t stb = stgb + (s ^ 1) * ATT_STAGE_B;
                const int kn0 = (t + 1) * 64;
#pragma unroll
                for (int j = 0; j < 4; j++) {
                    const int idx = j * 128 + tid;
                    const int r = idx >> 3, c = idx & 7;
                    const uint32_t off = (uint32_t)r * 128 + ((uint32_t)c ^ (uint32_t)(r & 7)) * 16;
                    const size_t g = (size_t)(kn0 + r) * DMODEL + hcol + c * 8;
                    cp16(stb + off,                  Khi + g);
                    cp16(stb + ATT_TILE_B + off,     Klo + g);
                    cp16(stb + 2 * ATT_TILE_B + off, Vhi + g);
                    cp16(stb + 3 * ATT_TILE_B + off, Vlo + g);
                }
                CP_COMMIT();
                CP_WAIT1();
            } else {
                CP_WAIT0();
            }
            __syncthreads();

            const int k0 = t * 64;
            if (wrow_max >= k0) {
                const bool nomask = (k0 + 63) <= wrow_min;
                const uint32_t stb = stgb + s * ATT_STAGE_B;

#pragma unroll
                for (int np = 0; np < 4; np++) {
                    if (k0 + np * 16 > wrow_max) continue;   // P would be exactly 0

                    float s8[2][8];
#pragma unroll
                    for (int mf = 0; mf < 2; mf++)
#pragma unroll
                        for (int e = 0; e < 8; e++) s8[mf][e] = 0.f;
#pragma unroll
                    for (int ks = 0; ks < 4; ks++) {
                        uint32_t kh[4], kl[4];
                        const uint32_t ka = stb + (uint32_t)np * 2048 + koff[ks];
                        ldsm4(kh, ka);
                        ldsm4(kl, ka + ATT_TILE_B);
#pragma unroll
                        for (int mf = 0; mf < 2; mf++) {
                            mma_bf16(&s8[mf][0], qh[mf][ks], kh[0], kh[1]);
                            mma_bf16(&s8[mf][0], qh[mf][ks], kl[0], kl[1]);
                            mma_bf16(&s8[mf][0], ql[mf][ks], kh[0], kh[1]);
                            mma_bf16(&s8[mf][4], qh[mf][ks], kh[2], kh[3]);
                            mma_bf16(&s8[mf][4], qh[mf][ks], kl[2], kl[3]);
                            mma_bf16(&s8[mf][4], ql[mf][ks], kh[2], kh[3]);
                        }
                    }

                    const int c0 = k0 + np * 16 + ((lane & 3) << 1);
                    uint32_t Ph[2][4], Pl[2][4];
#pragma unroll
                    for (int mf = 0; mf < 2; mf++) {
                        float p[8];
                        if (nomask) {
#pragma unroll
                            for (int e = 0; e < 8; e++) p[e] = __expf(s8[mf][e]);
                        } else {
                            p[0] = (c0     <= r0g[mf]) ? __expf(s8[mf][0]) : 0.f;
                            p[1] = (c0 + 1 <= r0g[mf]) ? __expf(s8[mf][1]) : 0.f;
                            p[2] = (c0     <= r1g[mf]) ? __expf(s8[mf][2]) : 0.f;
                            p[3] = (c0 + 1 <= r1g[mf]) ? __expf(s8[mf][3]) : 0.f;
                            p[4] = (c0 + 8 <= r0g[mf]) ? __expf(s8[mf][4]) : 0.f;
                            p[5] = (c0 + 9 <= r0g[mf]) ? __expf(s8[mf][5]) : 0.f;
                            p[6] = (c0 + 8 <= r1g[mf]) ? __expf(s8[mf][6]) : 0.f;
                            p[7] = (c0 + 9 <= r1g[mf]) ? __expf(s8[mf][7]) : 0.f;
                        }
                        l0[mf] += (p[0] + p[1]) + (p[4] + p[5]);
                        l1[mf] += (p[2] + p[3]) + (p[6] + p[7]);
#pragma unroll
                        for (int j = 0; j < 4; j++)
                            split2(p[2 * j], p[2 * j + 1], Ph[mf][j], Pl[mf][j]);
                    }

#pragma unroll
                    for (int dn = 0; dn < 4; dn++) {
                        uint32_t vh[4], vl[4];
                        const uint32_t va = stb + (uint32_t)np * 2048 + voff[dn];
                        ldsm4t(vh, va + 2 * ATT_TILE_B);
                        ldsm4t(vl, va + 3 * ATT_TILE_B);
#pragma unroll
                        for (int mf = 0; mf < 2; mf++) {
                            mma_bf16(O[mf][dn * 2],     Ph[mf], vh[0], vh[1]);
                            mma_bf16(O[mf][dn * 2 + 1], Ph[mf], vh[2], vh[3]);
                            mma_bf16(O[mf][dn * 2],     Ph[mf], vl[0], vl[1]);
                            mma_bf16(O[mf][dn * 2 + 1], Ph[mf], vl[2], vl[3]);
                            mma_bf16(O[mf][dn * 2],     Pl[mf], vh[0], vh[1]);
                            mma_bf16(O[mf][dn * 2 + 1], Pl[mf], vh[2], vh[3]);
                        }
                    }
                }
            }
            __syncthreads();
        }

        const int cbase = hcol + ((lane & 3) << 1);
#pragma unroll
        for (int mf = 0; mf < 2; mf++) {
            float a0 = l0[mf], a1 = l1[mf];
            a0 += __shfl_xor_sync(0xFFFFFFFF, a0, 1);
            a0 += __shfl_xor_sync(0xFFFFFFFF, a0, 2);
            a1 += __shfl_xor_sync(0xFFFFFFFF, a1, 1);
            a1 += __shfl_xor_sync(0xFFFFFFFF, a1, 2);
            const float inv0 = 1.f / a0, inv1 = 1.f / a1;
#pragma unroll
            for (int f = 0; f < 8; f++) {
                const size_t o0 = (size_t)r0g[mf] * DMODEL + cbase + f * 8;
                const size_t o1 = (size_t)r1g[mf] * DMODEL + cbase + f * 8;
                uint32_t hh, ll;
                split2(O[mf][f][0] * inv0, O[mf][f][1] * inv0, hh, ll);
                *(uint32_t*)&Chi[o0] = hh; *(uint32_t*)&Clo[o0] = ll;
                split2(O[mf][f][2] * inv1, O[mf][f][3] * inv1, hh, ll);
                *(uint32_t*)&Chi[o1] = hh; *(uint32_t*)&Clo[o1] = ll;
            }
        }
    }
}

// ---------------------------------------------------------------------------
extern "C" void kernel_launch(void* const* d_in, const int* in_sizes, int n_in,
                              void* d_out, int out_size)
{
    const float* x  = (const float*)d_in[0];
    const float* Wq = (const float*)d_in[1];
    const float* Wk = (const float*)d_in[2];
    const float* Wv = (const float*)d_in[3];
    const float* Wo = (const float*)d_in[4];
    float* out = (float*)d_out;

    float *Qp, *Kp;
    cudaGetSymbolAddress((void**)&Qp, g_Q);
    cudaGetSymbolAddress((void**)&Kp, g_K);

    __nv_bfloat16 *xhi, *xlo, *whi, *wlo, *chi, *clo;
    cudaGetSymbolAddress((void**)&xhi, g_xhi);
    cudaGetSymbolAddress((void**)&xlo, g_xlo);
    cudaGetSymbolAddress((void**)&whi, g_whi);
    cudaGetSymbolAddress((void**)&wlo, g_wlo);
    cudaGetSymbolAddress((void**)&chi, g_chi);
    cudaGetSymbolAddress((void**)&clo, g_clo);

    __nv_bfloat16 *qhi, *qlo, *khi, *klo, *vhi, *vlo;
    cudaGetSymbolAddress((void**)&qhi, g_qhi);
    cudaGetSymbolAddress((void**)&qlo, g_qlo);
    cudaGetSymbolAddress((void**)&khi, g_khi);
    cudaGetSymbolAddress((void**)&klo, g_klo);
    cudaGetSymbolAddress((void**)&vhi, g_vhi);
    cudaGetSymbolAddress((void**)&vlo, g_vlo);

    int* workp;
    cudaGetSymbolAddress((void**)&workp, g_attn_work);

    const int WSZ = DMODEL * DMODEL;

    static int attr_set = 0;
    if (!attr_set) {
        cudaFuncSetAttribute(gemm_qkv, cudaFuncAttributeMaxDynamicSharedMemorySize,
                             2 * STAGE_B);
        cudaFuncSetAttribute(gemm_tc, cudaFuncAttributeMaxDynamicSharedMemorySize,
                             2 * STAGE_B);
        cudaFuncSetAttribute(attn_tc, cudaFuncAttributeMaxDynamicSharedMemorySize,
                             ATT_SMEM);
        attr_set = 1;
    }

    // reset work counter (async memset is graph-capturable)
    cudaMemsetAsync(workp, 0, sizeof(int));

    split_kernel<<<(SEQ * DMODEL / 4 + 255) / 256, 256>>>(x, xhi, xlo, SEQ * DMODEL / 4);
    split_w4<<<dim3((WSZ / 4 + 255) / 256, 4), 256>>>(Wq, Wk, Wv, Wo, whi, wlo);

    gemm_qkv<<<dim3(DMODEL / 128, SEQ / 128, 3), 128, 2 * STAGE_B>>>(
        xhi, xlo, whi, wlo, Qp, Kp, vhi, vlo);

    rope_conv<<<(SEQ * DMODEL / 4 + 255) / 256, 256>>>(Qp, Kp, qhi, qlo, khi, klo);

    attn_tc<<<ATT_CTAS, 128, ATT_SMEM>>>(qhi, qlo, khi, klo, vhi, vlo, chi, clo);

    gemm_tc<<<dim3(DMODEL / 128, SEQ / 128), 128, 2 * STAGE_B>>>(
        chi, clo, whi + 3 * (size_t)WSZ, wlo + 3 * (size_t)WSZ, out);
}